// round 12
// baseline (speedup 1.0000x reference)
#include <cuda_runtime.h>
#include <cuda_bf16.h>
#include <cstdint>

#define NN 50000
#define NE 800000
#define DIM 96
#define NH 8
#define HD 12

// ============================ scratch ======================================
__device__ __align__(16) float g_Q[NN * DIM];
__device__ __align__(16) float g_K[NN * DIM];
__device__ __align__(16) float g_V[NN * DIM];
__device__ __align__(16) float g_E[NE * DIM];   // E = ea@We + be, fp32
__device__ int   g_is64;
// W^T images: [4 weights][hi/lo][96 rows (out j) x 104 cols (in k)] bf16
__device__ uint4 g_WT[4][2][1248];
// CSR machinery
__device__ int   g_deg[NN];
__device__ int   g_cnt[NN];
__device__ int   g_tmp[NN];
__device__ int   g_bsum[256];
__device__ int   g_boff[256];
__device__ int   g_scan_ctr;
__device__ int   g_srcs[NE];       // CSR-ordered src indices
__device__ int   g_eids[NE];       // CSR-ordered edge ids

// ============================ smem layout ==================================
#define SM_A  0
#define SM_BH 51200
#define SM_BL 71168
#define SMEM_BYTES 91136
#define ASTR 100   // fp32 stride (floats)
#define BSTR 104   // bf16 stride (elements)

#define ETILES 5
#define QTILES 4
#define NT 512

// ============================ helpers ======================================
__device__ __forceinline__ uint32_t smem_u32(const void* p) {
    uint32_t a;
    asm("{ .reg .u64 t; cvta.to.shared.u64 t, %1; cvt.u32.u64 %0, t; }" : "=r"(a) : "l"(p));
    return a;
}
__device__ __forceinline__ void cp16(uint32_t s, const void* g) {
    asm volatile("cp.async.ca.shared.global [%0], [%1], 16;" :: "r"(s), "l"(g));
}
#define CP_COMMIT() asm volatile("cp.async.commit_group;")
#define CP_WAIT0()  asm volatile("cp.async.wait_group 0;" ::: "memory")

__device__ __forceinline__ void mma_bf16(float c[4], uint32_t a0, uint32_t a1,
                                         uint32_t a2, uint32_t a3,
                                         uint32_t b0, uint32_t b1) {
    asm volatile(
        "mma.sync.aligned.m16n8k16.row.col.f32.bf16.bf16.f32 "
        "{%0,%1,%2,%3}, {%4,%5,%6,%7}, {%8,%9}, {%0,%1,%2,%3};"
        : "+f"(c[0]), "+f"(c[1]), "+f"(c[2]), "+f"(c[3])
        : "r"(a0), "r"(a1), "r"(a2), "r"(a3), "r"(b0), "r"(b1));
}

__device__ __forceinline__ void split2(float2 f, uint32_t& hi, uint32_t& lo) {
    __nv_bfloat16 h0 = __float2bfloat16(f.x), h1 = __float2bfloat16(f.y);
    __nv_bfloat16 l0 = __float2bfloat16(f.x - __bfloat162float(h0));
    __nv_bfloat16 l1 = __float2bfloat16(f.y - __bfloat162float(h1));
    hi = (uint32_t)__bfloat16_as_ushort(h0) | ((uint32_t)__bfloat16_as_ushort(h1) << 16);
    lo = (uint32_t)__bfloat16_as_ushort(l0) | ((uint32_t)__bfloat16_as_ushort(l1) << 16);
}

// Warp GEMM (16-warp variant): C[16][48] = A[r0..r0+15][0..95] @ W^T[nh half].
__device__ __forceinline__ void warp_gemm(const float* As, const char* smem,
                                          int r0, int nh, int lane, float acc[6][4]) {
#pragma unroll
    for (int n = 0; n < 6; n++)
#pragma unroll
        for (int i = 0; i < 4; i++) acc[n][i] = 0.f;

    const int ar = r0 + (lane >> 2);
    const int kc = (lane & 3) * 2;
    const int br = nh * 48 + (lane >> 2);
    const __nv_bfloat16* Bh = (const __nv_bfloat16*)(smem + SM_BH);
    const __nv_bfloat16* Bl = (const __nv_bfloat16*)(smem + SM_BL);

#pragma unroll
    for (int ks = 0; ks < 6; ks++) {
        int k0 = ks * 16;
        float2 f0 = *(const float2*)(As + (size_t)ar * ASTR + k0 + kc);
        float2 f1 = *(const float2*)(As + (size_t)(ar + 8) * ASTR + k0 + kc);
        float2 f2 = *(const float2*)(As + (size_t)ar * ASTR + k0 + kc + 8);
        float2 f3 = *(const float2*)(As + (size_t)(ar + 8) * ASTR + k0 + kc + 8);
        uint32_t ah0, ah1, ah2, ah3, al0, al1, al2, al3;
        split2(f0, ah0, al0); split2(f1, ah1, al1);
        split2(f2, ah2, al2); split2(f3, ah3, al3);
#pragma unroll
        for (int n = 0; n < 6; n++) {
            const __nv_bfloat16* bh = Bh + (size_t)(n * 8 + br) * BSTR + k0 + kc;
            const __nv_bfloat16* bl = Bl + (size_t)(n * 8 + br) * BSTR + k0 + kc;
            uint32_t b0 = *(const uint32_t*)(bh);
            uint32_t b1 = *(const uint32_t*)(bh + 8);
            uint32_t c0 = *(const uint32_t*)(bl);
            uint32_t c1 = *(const uint32_t*)(bl + 8);
            mma_bf16(acc[n], ah0, ah1, ah2, ah3, b0, b1);
            mma_bf16(acc[n], al0, al1, al2, al3, b0, b1);
            mma_bf16(acc[n], ah0, ah1, ah2, ah3, c0, c1);
        }
    }
}

// =========================== prep ==========================================
__global__ void prep_kernel(const float* __restrict__ Wq, const float* __restrict__ Wk,
                            const float* __restrict__ Wv, const float* __restrict__ We,
                            const int* __restrict__ eidx) {
    const float* W = (blockIdx.x == 0) ? Wq : (blockIdx.x == 1) ? Wk
                   : (blockIdx.x == 2) ? Wv : We;
    unsigned short* hi = (unsigned short*)g_WT[blockIdx.x][0];
    unsigned short* lo = (unsigned short*)g_WT[blockIdx.x][1];
    int zb = blockIdx.x * 12500;
    for (int i = threadIdx.x; i < 12500; i += blockDim.x) { g_deg[zb + i] = 0; g_cnt[zb + i] = 0; }
    if (blockIdx.x == 0 && threadIdx.x == 0) g_scan_ctr = 0;
    if (blockIdx.x == 3 && threadIdx.x == 0) {
        int acc = 0;
        for (int i = 0; i < 256; i++) acc |= eidx[2 * i + 1];
        g_is64 = (acc == 0) ? 1 : 0;
    }
    for (int i = threadIdx.x; i < 96 * BSTR; i += blockDim.x) { hi[i] = 0; lo[i] = 0; }
    __syncthreads();
    for (int i = threadIdx.x; i < 96 * 96; i += blockDim.x) {
        int k = i / 96, j = i - k * 96;
        float v = W[i];
        __nv_bfloat16 h = __float2bfloat16(v);
        __nv_bfloat16 l = __float2bfloat16(v - __bfloat162float(h));
        hi[j * BSTR + k] = __bfloat16_as_ushort(h);
        lo[j * BSTR + k] = __bfloat16_as_ushort(l);
    }
}

// =========================== hist ==========================================
__global__ void hist_kernel(const int* __restrict__ eidx) {
    int e = blockIdx.x * blockDim.x + threadIdx.x;
    if (e < NE) {
        int dst = g_is64 ? __ldg(eidx + 2 * (NE + e)) : __ldg(eidx + NE + e);
        atomicAdd(&g_deg[dst], 1);
    }
}

// =========================== scan ==========================================
__global__ void scan12_kernel() {
    int tid = threadIdx.x;
    int i = blockIdx.x * 256 + tid;
    int v = (i < NN) ? g_deg[i] : 0;
    int lane = tid & 31, w = tid >> 5;
    int x = v;
#pragma unroll
    for (int o = 1; o < 32; o <<= 1) {
        int t = __shfl_up_sync(0xFFFFFFFFu, x, o);
        if (lane >= o) x += t;
    }
    __shared__ int ws[8];
    __shared__ int is_last;
    if (lane == 31) ws[w] = x;
    __syncthreads();
    if (w == 0) {
        int s = (lane < 8) ? ws[lane] : 0;
#pragma unroll
        for (int o = 1; o < 8; o <<= 1) {
            int t = __shfl_up_sync(0xFFFFFFFFu, s, o);
            if (lane >= o) s += t;
        }
        if (lane < 8) ws[lane] = s;
    }
    __syncthreads();
    int excl = x - v + (w > 0 ? ws[w - 1] : 0);
    if (i < NN) g_tmp[i] = excl;
    if (tid == 255) {
        g_bsum[blockIdx.x] = excl + v;
        __threadfence();
    }
    __syncthreads();
    if (tid == 0) is_last = (atomicAdd(&g_scan_ctr, 1) == 195) ? 1 : 0;
    __syncthreads();
    if (is_last) {
        __threadfence();
        int v2 = (tid < 196) ? __ldcg(&g_bsum[tid]) : 0;
        int x2 = v2;
#pragma unroll
        for (int o = 1; o < 32; o <<= 1) {
            int t = __shfl_up_sync(0xFFFFFFFFu, x2, o);
            if (lane >= o) x2 += t;
        }
        __syncthreads();
        if (lane == 31) ws[w] = x2;
        __syncthreads();
        if (w == 0) {
            int s = (lane < 8) ? ws[lane] : 0;
#pragma unroll
            for (int o = 1; o < 8; o <<= 1) {
                int t = __shfl_up_sync(0xFFFFFFFFu, s, o);
                if (lane >= o) s += t;
            }
            if (lane < 8) ws[lane] = s;
        }
        __syncthreads();
        if (tid < 196) g_boff[tid] = x2 - v2 + (w > 0 ? ws[w - 1] : 0);
    }
}

// =========================== scatter =======================================
__global__ void scatter_kernel(const int* __restrict__ eidx) {
    int e = blockIdx.x * blockDim.x + threadIdx.x;
    if (e < NE) {
        int src, dst;
        if (g_is64) { src = __ldg(eidx + 2 * e); dst = __ldg(eidx + 2 * (NE + e)); }
        else        { src = __ldg(eidx + e);     dst = __ldg(eidx + NE + e); }
        int base = __ldg(&g_tmp[dst]) + __ldg(&g_boff[dst >> 8]);
        int pos = base + atomicAdd(&g_cnt[dst], 1);
        g_srcs[pos] = src;
        g_eids[pos] = e;
    }
}

// ============================ QKV ==========================================
__global__ void __launch_bounds__(NT, 2)
qkv_kernel(const float* __restrict__ x,
           const float* __restrict__ bq, const float* __restrict__ bk,
           const float* __restrict__ bv) {
    extern __shared__ __align__(16) char smem[];
    uint32_t sb = smem_u32(smem);
    int tid = threadIdx.x, wid = tid >> 5, lane = tid & 31;
    int mslab = wid >> 1, nh = wid & 1;
    int w = blockIdx.y;
    const float* bias = (w == 0) ? bq : (w == 1) ? bk : bv;
    float* out = (w == 0) ? g_Q : (w == 1) ? g_K : g_V;

    {
        const uint4* sh = g_WT[w][0];
        const uint4* sl = g_WT[w][1];
        for (int i = tid; i < 1248; i += NT) {
            cp16(sb + SM_BH + i * 16, sh + i);
            cp16(sb + SM_BL + i * 16, sl + i);
        }
    }
    int tile0 = blockIdx.x * QTILES;
    {
        int row0 = tile0 * 128;
        for (int i = tid; i < 3072; i += NT) {
            int r = i / 24, q = i - r * 24;
            int n = row0 + r;
            if (n < NN)
                cp16(sb + SM_A + (uint32_t)(r * ASTR + q * 4) * 4, x + (size_t)n * 96 + q * 4);
        }
    }
    CP_COMMIT();

    for (int t = 0; t < QTILES; t++) {
        int row0 = (tile0 + t) * 128;
        if (row0 >= NN) break;
        CP_WAIT0();
        __syncthreads();

        float acc[6][4];
        warp_gemm((const float*)smem, smem, mslab * 16, nh, lane, acc);
        __syncthreads();

        if (t + 1 < QTILES) {
            int nrow0 = (tile0 + t + 1) * 128;
            if (nrow0 < NN) {
                for (int i = tid; i < 3072; i += NT) {
                    int r = i / 24, q = i - r * 24;
                    int n = nrow0 + r;
                    if (n < NN)
                        cp16(sb + SM_A + (uint32_t)(r * ASTR + q * 4) * 4,
                             x + (size_t)n * 96 + q * 4);
                }
            }
            CP_COMMIT();
        }

        int rl = row0 + mslab * 16 + (lane >> 2);
        int cb = (lane & 3) * 2;
#pragma unroll
        for (int n = 0; n < 6; n++) {
            int col = nh * 48 + n * 8 + cb;
            float b0 = __ldg(bias + col), b1 = __ldg(bias + col + 1);
            if (rl < NN)
                *(float2*)(out + (size_t)rl * 96 + col) = make_float2(acc[n][0] + b0, acc[n][1] + b1);
            if (rl + 8 < NN)
                *(float2*)(out + (size_t)(rl + 8) * 96 + col) = make_float2(acc[n][2] + b0, acc[n][3] + b1);
        }
    }
}

// ============================ Edge GEMM ====================================
__global__ void __launch_bounds__(NT, 2)
egemm_kernel(const float* __restrict__ edge_attr, const float* __restrict__ be) {
    extern __shared__ __align__(16) char smem[];
    uint32_t sb = smem_u32(smem);
    int tid = threadIdx.x, wid = tid >> 5, lane = tid & 31;
    int mslab = wid >> 1, nh = wid & 1;

    {
        const uint4* sh = g_WT[3][0];
        const uint4* sl = g_WT[3][1];
        for (int i = tid; i < 1248; i += NT) {
            cp16(sb + SM_BH + i * 16, sh + i);
            cp16(sb + SM_BL + i * 16, sl + i);
        }
    }
    int tile0 = blockIdx.x * ETILES;
    {
        int e0 = tile0 * 128;
        for (int i = tid; i < 3072; i += NT) {
            int r = i / 24, q = i - r * 24;
            cp16(sb + SM_A + (uint32_t)(r * ASTR + q * 4) * 4,
                 edge_attr + (size_t)(e0 + r) * 96 + q * 4);
        }
    }
    CP_COMMIT();

    for (int t = 0; t < ETILES; t++) {
        int e0 = (tile0 + t) * 128;
        CP_WAIT0();
        __syncthreads();

        float acc[6][4];
        warp_gemm((const float*)smem, smem, mslab * 16, nh, lane, acc);
        __syncthreads();

        if (t + 1 < ETILES) {
            int ne0 = (tile0 + t + 1) * 128;
            for (int i = tid; i < 3072; i += NT) {
                int r = i / 24, q = i - r * 24;
                cp16(sb + SM_A + (uint32_t)(r * ASTR + q * 4) * 4,
                     edge_attr + (size_t)(ne0 + r) * 96 + q * 4);
            }
            CP_COMMIT();
        }

        int rl = e0 + mslab * 16 + (lane >> 2);
        int cb = (lane & 3) * 2;
#pragma unroll
        for (int n = 0; n < 6; n++) {
            int col = nh * 48 + n * 8 + cb;
            float b0 = __ldg(be + col), b1 = __ldg(be + col + 1);
            *(float2*)(g_E + (size_t)rl * 96 + col) = make_float2(acc[n][0] + b0, acc[n][1] + b1);
            *(float2*)(g_E + (size_t)(rl + 8) * 96 + col) = make_float2(acc[n][2] + b0, acc[n][3] + b1);
        }
    }
}

// ============================ Fused score + aggregate ======================
// One warp per dst node. 24 active lanes, lane t owns cols 4t..4t+3 (float4);
// head h = t/3 (lanes 3h,3h+1,3h+2 cover cols 12h..12h+11).
// Per edge: 3 x LDG.128 + 2 shfl_down partial-sum + exp + 1 shfl broadcast.
__global__ void __launch_bounds__(256)
agg_kernel(float* __restrict__ out) {
    int wid = threadIdx.x >> 5, lane = threadIdx.x & 31;
    int n = blockIdx.x * 8 + wid;
    int r0 = __ldg(&g_tmp[n]) + __ldg(&g_boff[n >> 8]);
    int r1 = (n == NN - 1) ? NE : __ldg(&g_tmp[n + 1]) + __ldg(&g_boff[(n + 1) >> 8]);

    bool active = lane < 24;
    int c0 = active ? lane * 4 : 0;           // safe col for inactive lanes
    int leader = (lane / 3) * 3;              // head-group leader lane
    const float inv_sqrt_d = 0.28867513459481287f;

    float4 q4 = *(const float4*)(g_Q + (size_t)n * 96 + c0);

    float4 a4 = make_float4(0.f, 0.f, 0.f, 0.f);
    float z = 0.f;
#pragma unroll 2
    for (int j = r0; j < r1; j++) {
        int src = __ldg(g_srcs + j);
        int eid = __ldg(g_eids + j);
        float4 e4 = __ldg((const float4*)(g_E + (size_t)eid * 96 + c0));
        float4 k4 = __ldg((const float4*)(g_K + (size_t)src * 96 + c0));
        float4 v4 = __ldg((const float4*)(g_V + (size_t)src * 96 + c0));

        float p = (k4.x * q4.x) * e4.x + (k4.y * q4.y) * e4.y
                + (k4.z * q4.z) * e4.z + (k4.w * q4.w) * e4.w;
        float p1 = __shfl_down_sync(0xFFFFFFFFu, p, 1);
        float p2 = __shfl_down_sync(0xFFFFFFFFu, p, 2);
        float s = (p + p1 + p2) * inv_sqrt_d;     // correct at leader lanes
        s = fminf(5.0f, fmaxf(-5.0f, s));
        s = __expf(s);
        s = __shfl_sync(0xFFFFFFFFu, s, leader);  // broadcast head score

        a4.x = fmaf(v4.x, s, a4.x);
        a4.y = fmaf(v4.y, s, a4.y);
        a4.z = fmaf(v4.z, s, a4.z);
        a4.w = fmaf(v4.w, s, a4.w);
        z += s;
    }
    if (active) {
        float inv = 1.0f / (z + 1e-6f);
        float4 r;
        r.x = a4.x * inv; r.y = a4.y * inv; r.z = a4.z * inv; r.w = a4.w * inv;
        *(float4*)(out + (size_t)n * 96 + c0) = r;
    }
}

// ============================ launch =======================================
static cudaStream_t s_aux1 = nullptr;
static cudaStream_t s_aux2 = nullptr;
static cudaEvent_t  s_ev_fork = nullptr;
static cudaEvent_t  s_ev_j1 = nullptr;
static cudaEvent_t  s_ev_j2 = nullptr;

extern "C" void kernel_launch(void* const* d_in, const int* in_sizes, int n_in,
                              void* d_out, int out_size) {
    const float* x    = (const float*)d_in[0];
    const int*   eidx = (const int*)  d_in[1];
    const float* ea   = (const float*)d_in[2];
    const float* Wq   = (const float*)d_in[3];
    const float* bq   = (const float*)d_in[4];
    const float* Wk   = (const float*)d_in[5];
    const float* bk   = (const float*)d_in[6];
    const float* We   = (const float*)d_in[7];
    const float* be   = (const float*)d_in[8];
    const float* Wv   = (const float*)d_in[9];
    const float* bv   = (const float*)d_in[10];
    float* out = (float*)d_out;

    if (s_aux1 == nullptr) {
        cudaStreamCreateWithFlags(&s_aux1, cudaStreamNonBlocking);
        cudaStreamCreateWithFlags(&s_aux2, cudaStreamNonBlocking);
        cudaEventCreateWithFlags(&s_ev_fork, cudaEventDisableTiming);
        cudaEventCreateWithFlags(&s_ev_j1, cudaEventDisableTiming);
        cudaEventCreateWithFlags(&s_ev_j2, cudaEventDisableTiming);
    }

    cudaFuncSetAttribute(qkv_kernel,   cudaFuncAttributeMaxDynamicSharedMemorySize, SMEM_BYTES);
    cudaFuncSetAttribute(egemm_kernel, cudaFuncAttributeMaxDynamicSharedMemorySize, SMEM_BYTES);

    // main stream: prep, then fork
    prep_kernel<<<4, 256>>>(Wq, Wk, Wv, We, eidx);
    cudaEventRecord(s_ev_fork, 0);
    cudaStreamWaitEvent(s_aux1, s_ev_fork, 0);
    cudaStreamWaitEvent(s_aux2, s_ev_fork, 0);

    // aux1: CSR build
    hist_kernel<<<(NE + 255) / 256, 256, 0, s_aux1>>>(eidx);
    scan12_kernel<<<196, 256, 0, s_aux1>>>();
    scatter_kernel<<<(NE + 255) / 256, 256, 0, s_aux1>>>(eidx);
    cudaEventRecord(s_ev_j1, s_aux1);

    // aux2: edge GEMM
    egemm_kernel<<<NE / (128 * ETILES), NT, SMEM_BYTES, s_aux2>>>(ea, be);
    cudaEventRecord(s_ev_j2, s_aux2);

    // main: QKV GEMMs (overlap CSR build + edge GEMM)
    qkv_kernel<<<dim3(98, 3), NT, SMEM_BYTES>>>(x, bq, bk, bv);

    // join, then fused score+aggregate
    cudaStreamWaitEvent(0, s_ev_j1, 0);
    cudaStreamWaitEvent(0, s_ev_j2, 0);
    agg_kernel<<<NN / 8, 256>>>(out);
}

// round 13
// speedup vs baseline: 1.0205x; 1.0205x over previous
#include <cuda_runtime.h>
#include <cuda_bf16.h>
#include <cstdint>

#define NN 50000
#define NE 800000
#define DIM 96
#define NH 8
#define HD 12

// ============================ scratch ======================================
__device__ __align__(16) float g_Q[NN * DIM];
__device__ __align__(16) float g_K[NN * DIM];
__device__ __align__(16) float g_V[NN * DIM];
__device__ __align__(16) float g_E[NE * DIM];   // E = ea@We + be, fp32
__device__ int   g_is64;
__device__ uint4 g_WT[4][2][1248];
// CSR machinery
__device__ int   g_deg[NN];
__device__ int   g_cnt[NN];
__device__ int   g_tmp[NN];
__device__ int   g_bsum[256];
__device__ int   g_boff[256];
__device__ int   g_scan_ctr;
__device__ int   g_srcs[NE];
__device__ int   g_eids[NE];

// ============================ smem layout ==================================
#define SM_A  0
#define SM_BH 51200
#define SM_BL 71168
#define SMEM_BYTES 91136
#define ASTR 100
#define BSTR 104

#define ETILES 5
#define QTILES 4
#define NT 512

// ============================ helpers ======================================
__device__ __forceinline__ uint32_t smem_u32(const void* p) {
    uint32_t a;
    asm("{ .reg .u64 t; cvta.to.shared.u64 t, %1; cvt.u32.u64 %0, t; }" : "=r"(a) : "l"(p));
    return a;
}
__device__ __forceinline__ void cp16(uint32_t s, const void* g) {
    asm volatile("cp.async.ca.shared.global [%0], [%1], 16;" :: "r"(s), "l"(g));
}
#define CP_COMMIT() asm volatile("cp.async.commit_group;")
#define CP_WAIT0()  asm volatile("cp.async.wait_group 0;" ::: "memory")

__device__ __forceinline__ void mma_bf16(float c[4], uint32_t a0, uint32_t a1,
                                         uint32_t a2, uint32_t a3,
                                         uint32_t b0, uint32_t b1) {
    asm volatile(
        "mma.sync.aligned.m16n8k16.row.col.f32.bf16.bf16.f32 "
        "{%0,%1,%2,%3}, {%4,%5,%6,%7}, {%8,%9}, {%0,%1,%2,%3};"
        : "+f"(c[0]), "+f"(c[1]), "+f"(c[2]), "+f"(c[3])
        : "r"(a0), "r"(a1), "r"(a2), "r"(a3), "r"(b0), "r"(b1));
}

__device__ __forceinline__ void split2(float2 f, uint32_t& hi, uint32_t& lo) {
    __nv_bfloat16 h0 = __float2bfloat16(f.x), h1 = __float2bfloat16(f.y);
    __nv_bfloat16 l0 = __float2bfloat16(f.x - __bfloat162float(h0));
    __nv_bfloat16 l1 = __float2bfloat16(f.y - __bfloat162float(h1));
    hi = (uint32_t)__bfloat16_as_ushort(h0) | ((uint32_t)__bfloat16_as_ushort(h1) << 16);
    lo = (uint32_t)__bfloat16_as_ushort(l0) | ((uint32_t)__bfloat16_as_ushort(l1) << 16);
}

// Warp GEMM (16-warp variant): C[16][48] = A[r0..r0+15][0..95] @ W^T[nh half].
__device__ __forceinline__ void warp_gemm(const float* As, const char* smem,
                                          int r0, int nh, int lane, float acc[6][4]) {
#pragma unroll
    for (int n = 0; n < 6; n++)
#pragma unroll
        for (int i = 0; i < 4; i++) acc[n][i] = 0.f;

    const int ar = r0 + (lane >> 2);
    const int kc = (lane & 3) * 2;
    const int br = nh * 48 + (lane >> 2);
    const __nv_bfloat16* Bh = (const __nv_bfloat16*)(smem + SM_BH);
    const __nv_bfloat16* Bl = (const __nv_bfloat16*)(smem + SM_BL);

#pragma unroll
    for (int ks = 0; ks < 6; ks++) {
        int k0 = ks * 16;
        float2 f0 = *(const float2*)(As + (size_t)ar * ASTR + k0 + kc);
        float2 f1 = *(const float2*)(As + (size_t)(ar + 8) * ASTR + k0 + kc);
        float2 f2 = *(const float2*)(As + (size_t)ar * ASTR + k0 + kc + 8);
        float2 f3 = *(const float2*)(As + (size_t)(ar + 8) * ASTR + k0 + kc + 8);
        uint32_t ah0, ah1, ah2, ah3, al0, al1, al2, al3;
        split2(f0, ah0, al0); split2(f1, ah1, al1);
        split2(f2, ah2, al2); split2(f3, ah3, al3);
#pragma unroll
        for (int n = 0; n < 6; n++) {
            const __nv_bfloat16* bh = Bh + (size_t)(n * 8 + br) * BSTR + k0 + kc;
            const __nv_bfloat16* bl = Bl + (size_t)(n * 8 + br) * BSTR + k0 + kc;
            uint32_t b0 = *(const uint32_t*)(bh);
            uint32_t b1 = *(const uint32_t*)(bh + 8);
            uint32_t c0 = *(const uint32_t*)(bl);
            uint32_t c1 = *(const uint32_t*)(bl + 8);
            mma_bf16(acc[n], ah0, ah1, ah2, ah3, b0, b1);
            mma_bf16(acc[n], al0, al1, al2, al3, b0, b1);
            mma_bf16(acc[n], ah0, ah1, ah2, ah3, c0, c1);
        }
    }
}

// =========================== prep ==========================================
__global__ void prep_kernel(const float* __restrict__ Wq, const float* __restrict__ Wk,
                            const float* __restrict__ Wv, const float* __restrict__ We,
                            const int* __restrict__ eidx) {
    const float* W = (blockIdx.x == 0) ? Wq : (blockIdx.x == 1) ? Wk
                   : (blockIdx.x == 2) ? Wv : We;
    unsigned short* hi = (unsigned short*)g_WT[blockIdx.x][0];
    unsigned short* lo = (unsigned short*)g_WT[blockIdx.x][1];
    int zb = blockIdx.x * 12500;
    for (int i = threadIdx.x; i < 12500; i += blockDim.x) { g_deg[zb + i] = 0; g_cnt[zb + i] = 0; }
    if (blockIdx.x == 0 && threadIdx.x == 0) g_scan_ctr = 0;
    if (blockIdx.x == 3 && threadIdx.x == 0) {
        int acc = 0;
        for (int i = 0; i < 256; i++) acc |= eidx[2 * i + 1];
        g_is64 = (acc == 0) ? 1 : 0;
    }
    for (int i = threadIdx.x; i < 96 * BSTR; i += blockDim.x) { hi[i] = 0; lo[i] = 0; }
    __syncthreads();
    for (int i = threadIdx.x; i < 96 * 96; i += blockDim.x) {
        int k = i / 96, j = i - k * 96;
        float v = W[i];
        __nv_bfloat16 h = __float2bfloat16(v);
        __nv_bfloat16 l = __float2bfloat16(v - __bfloat162float(h));
        hi[j * BSTR + k] = __bfloat16_as_ushort(h);
        lo[j * BSTR + k] = __bfloat16_as_ushort(l);
    }
}

// =========================== hist ==========================================
__global__ void hist_kernel(const int* __restrict__ eidx) {
    int e = blockIdx.x * blockDim.x + threadIdx.x;
    if (e < NE) {
        int dst = g_is64 ? __ldg(eidx + 2 * (NE + e)) : __ldg(eidx + NE + e);
        atomicAdd(&g_deg[dst], 1);
    }
}

// =========================== scan ==========================================
__global__ void scan12_kernel() {
    int tid = threadIdx.x;
    int i = blockIdx.x * 256 + tid;
    int v = (i < NN) ? g_deg[i] : 0;
    int lane = tid & 31, w = tid >> 5;
    int x = v;
#pragma unroll
    for (int o = 1; o < 32; o <<= 1) {
        int t = __shfl_up_sync(0xFFFFFFFFu, x, o);
        if (lane >= o) x += t;
    }
    __shared__ int ws[8];
    __shared__ int is_last;
    if (lane == 31) ws[w] = x;
    __syncthreads();
    if (w == 0) {
        int s = (lane < 8) ? ws[lane] : 0;
#pragma unroll
        for (int o = 1; o < 8; o <<= 1) {
            int t = __shfl_up_sync(0xFFFFFFFFu, s, o);
            if (lane >= o) s += t;
        }
        if (lane < 8) ws[lane] = s;
    }
    __syncthreads();
    int excl = x - v + (w > 0 ? ws[w - 1] : 0);
    if (i < NN) g_tmp[i] = excl;
    if (tid == 255) {
        g_bsum[blockIdx.x] = excl + v;
        __threadfence();
    }
    __syncthreads();
    if (tid == 0) is_last = (atomicAdd(&g_scan_ctr, 1) == 195) ? 1 : 0;
    __syncthreads();
    if (is_last) {
        __threadfence();
        int v2 = (tid < 196) ? __ldcg(&g_bsum[tid]) : 0;
        int x2 = v2;
#pragma unroll
        for (int o = 1; o < 32; o <<= 1) {
            int t = __shfl_up_sync(0xFFFFFFFFu, x2, o);
            if (lane >= o) x2 += t;
        }
        __syncthreads();
        if (lane == 31) ws[w] = x2;
        __syncthreads();
        if (w == 0) {
            int s = (lane < 8) ? ws[lane] : 0;
#pragma unroll
            for (int o = 1; o < 8; o <<= 1) {
                int t = __shfl_up_sync(0xFFFFFFFFu, s, o);
                if (lane >= o) s += t;
            }
            if (lane < 8) ws[lane] = s;
        }
        __syncthreads();
        if (tid < 196) g_boff[tid] = x2 - v2 + (w > 0 ? ws[w - 1] : 0);
    }
}

// =========================== scatter =======================================
__global__ void scatter_kernel(const int* __restrict__ eidx) {
    int e = blockIdx.x * blockDim.x + threadIdx.x;
    if (e < NE) {
        int src, dst;
        if (g_is64) { src = __ldg(eidx + 2 * e); dst = __ldg(eidx + 2 * (NE + e)); }
        else        { src = __ldg(eidx + e);     dst = __ldg(eidx + NE + e); }
        int base = __ldg(&g_tmp[dst]) + __ldg(&g_boff[dst >> 8]);
        int pos = base + atomicAdd(&g_cnt[dst], 1);
        g_srcs[pos] = src;
        g_eids[pos] = e;
    }
}

// ============================ QKV ==========================================
__global__ void __launch_bounds__(NT, 2)
qkv_kernel(const float* __restrict__ x,
           const float* __restrict__ bq, const float* __restrict__ bk,
           const float* __restrict__ bv) {
    extern __shared__ __align__(16) char smem[];
    uint32_t sb = smem_u32(smem);
    int tid = threadIdx.x, wid = tid >> 5, lane = tid & 31;
    int mslab = wid >> 1, nh = wid & 1;
    int w = blockIdx.y;
    const float* bias = (w == 0) ? bq : (w == 1) ? bk : bv;
    float* out = (w == 0) ? g_Q : (w == 1) ? g_K : g_V;

    {
        const uint4* sh = g_WT[w][0];
        const uint4* sl = g_WT[w][1];
        for (int i = tid; i < 1248; i += NT) {
            cp16(sb + SM_BH + i * 16, sh + i);
            cp16(sb + SM_BL + i * 16, sl + i);
        }
    }
    int tile0 = blockIdx.x * QTILES;
    {
        int row0 = tile0 * 128;
        for (int i = tid; i < 3072; i += NT) {
            int r = i / 24, q = i - r * 24;
            int n = row0 + r;
            if (n < NN)
                cp16(sb + SM_A + (uint32_t)(r * ASTR + q * 4) * 4, x + (size_t)n * 96 + q * 4);
        }
    }
    CP_COMMIT();

    for (int t = 0; t < QTILES; t++) {
        int row0 = (tile0 + t) * 128;
        if (row0 >= NN) break;
        CP_WAIT0();
        __syncthreads();

        float acc[6][4];
        warp_gemm((const float*)smem, smem, mslab * 16, nh, lane, acc);
        __syncthreads();

        if (t + 1 < QTILES) {
            int nrow0 = (tile0 + t + 1) * 128;
            if (nrow0 < NN) {
                for (int i = tid; i < 3072; i += NT) {
                    int r = i / 24, q = i - r * 24;
                    int n = nrow0 + r;
                    if (n < NN)
                        cp16(sb + SM_A + (uint32_t)(r * ASTR + q * 4) * 4,
                             x + (size_t)n * 96 + q * 4);
                }
            }
            CP_COMMIT();
        }

        int rl = row0 + mslab * 16 + (lane >> 2);
        int cb = (lane & 3) * 2;
#pragma unroll
        for (int n = 0; n < 6; n++) {
            int col = nh * 48 + n * 8 + cb;
            float b0 = __ldg(bias + col), b1 = __ldg(bias + col + 1);
            if (rl < NN)
                *(float2*)(out + (size_t)rl * 96 + col) = make_float2(acc[n][0] + b0, acc[n][1] + b1);
            if (rl + 8 < NN)
                *(float2*)(out + (size_t)(rl + 8) * 96 + col) = make_float2(acc[n][2] + b0, acc[n][3] + b1);
        }
    }
}

// ============================ Edge GEMM ====================================
__global__ void __launch_bounds__(NT, 2)
egemm_kernel(const float* __restrict__ edge_attr, const float* __restrict__ be) {
    extern __shared__ __align__(16) char smem[];
    uint32_t sb = smem_u32(smem);
    int tid = threadIdx.x, wid = tid >> 5, lane = tid & 31;
    int mslab = wid >> 1, nh = wid & 1;

    {
        const uint4* sh = g_WT[3][0];
        const uint4* sl = g_WT[3][1];
        for (int i = tid; i < 1248; i += NT) {
            cp16(sb + SM_BH + i * 16, sh + i);
            cp16(sb + SM_BL + i * 16, sl + i);
        }
    }
    int tile0 = blockIdx.x * ETILES;
    {
        int e0 = tile0 * 128;
        for (int i = tid; i < 3072; i += NT) {
            int r = i / 24, q = i - r * 24;
            cp16(sb + SM_A + (uint32_t)(r * ASTR + q * 4) * 4,
                 edge_attr + (size_t)(e0 + r) * 96 + q * 4);
        }
    }
    CP_COMMIT();

    for (int t = 0; t < ETILES; t++) {
        int e0 = (tile0 + t) * 128;
        CP_WAIT0();
        __syncthreads();

        float acc[6][4];
        warp_gemm((const float*)smem, smem, mslab * 16, nh, lane, acc);
        __syncthreads();

        if (t + 1 < ETILES) {
            int ne0 = (tile0 + t + 1) * 128;
            for (int i = tid; i < 3072; i += NT) {
                int r = i / 24, q = i - r * 24;
                cp16(sb + SM_A + (uint32_t)(r * ASTR + q * 4) * 4,
                     edge_attr + (size_t)(ne0 + r) * 96 + q * 4);
            }
            CP_COMMIT();
        }

        int rl = e0 + mslab * 16 + (lane >> 2);
        int cb = (lane & 3) * 2;
#pragma unroll
        for (int n = 0; n < 6; n++) {
            int col = nh * 48 + n * 8 + cb;
            float b0 = __ldg(be + col), b1 = __ldg(be + col + 1);
            *(float2*)(g_E + (size_t)rl * 96 + col) = make_float2(acc[n][0] + b0, acc[n][1] + b1);
            *(float2*)(g_E + (size_t)(rl + 8) * 96 + col) = make_float2(acc[n][2] + b0, acc[n][3] + b1);
        }
    }
}

// ============================ Fused score + aggregate ======================
// One warp per dst node (R11 layout: lane owns cols 3t..3t+2, head = t>>2).
// Explicit 4-edge software pipeline: batch all loads, then 4 interleaved
// shfl-reduction chains, 4 exps, then FMAs — hides the per-edge dependent
// chain (LDG -> shfl x2 -> exp) across 4 independent edges.
__global__ void __launch_bounds__(256)
agg_kernel(float* __restrict__ out) {
    int wid = threadIdx.x >> 5, lane = threadIdx.x & 31;
    int n = blockIdx.x * 8 + wid;
    int r0 = __ldg(&g_tmp[n]) + __ldg(&g_boff[n >> 8]);
    int r1 = (n == NN - 1) ? NE : __ldg(&g_tmp[n + 1]) + __ldg(&g_boff[(n + 1) >> 8]);
    int c0 = lane * 3;
    const float inv_sqrt_d = 0.28867513459481287f;

    const float* qp = g_Q + (size_t)n * 96 + c0;
    float q0 = __ldg(qp + 0), q1 = __ldg(qp + 1), q2 = __ldg(qp + 2);

    float a0 = 0.f, a1 = 0.f, a2 = 0.f, z = 0.f;
    int j = r0;
    for (; j + 4 <= r1; j += 4) {
        // ---- batched index loads (8 LDG in flight) ----
        int sA = __ldg(g_srcs + j + 0), sB = __ldg(g_srcs + j + 1);
        int sC = __ldg(g_srcs + j + 2), sD = __ldg(g_srcs + j + 3);
        int eA = __ldg(g_eids + j + 0), eB = __ldg(g_eids + j + 1);
        int eC = __ldg(g_eids + j + 2), eD = __ldg(g_eids + j + 3);

        const float* EpA = g_E + (size_t)eA * 96 + c0;
        const float* EpB = g_E + (size_t)eB * 96 + c0;
        const float* EpC = g_E + (size_t)eC * 96 + c0;
        const float* EpD = g_E + (size_t)eD * 96 + c0;
        const float* KpA = g_K + (size_t)sA * 96 + c0;
        const float* KpB = g_K + (size_t)sB * 96 + c0;
        const float* KpC = g_K + (size_t)sC * 96 + c0;
        const float* KpD = g_K + (size_t)sD * 96 + c0;
        const float* VpA = g_V + (size_t)sA * 96 + c0;
        const float* VpB = g_V + (size_t)sB * 96 + c0;
        const float* VpC = g_V + (size_t)sC * 96 + c0;
        const float* VpD = g_V + (size_t)sD * 96 + c0;

        // ---- batched data loads (36 LDG in flight) ----
        float eA0 = __ldg(EpA + 0), eA1 = __ldg(EpA + 1), eA2 = __ldg(EpA + 2);
        float eB0 = __ldg(EpB + 0), eB1 = __ldg(EpB + 1), eB2 = __ldg(EpB + 2);
        float eC0 = __ldg(EpC + 0), eC1 = __ldg(EpC + 1), eC2 = __ldg(EpC + 2);
        float eD0 = __ldg(EpD + 0), eD1 = __ldg(EpD + 1), eD2 = __ldg(EpD + 2);
        float kA0 = __ldg(KpA + 0), kA1 = __ldg(KpA + 1), kA2 = __ldg(KpA + 2);
        float kB0 = __ldg(KpB + 0), kB1 = __ldg(KpB + 1), kB2 = __ldg(KpB + 2);
        float kC0 = __ldg(KpC + 0), kC1 = __ldg(KpC + 1), kC2 = __ldg(KpC + 2);
        float kD0 = __ldg(KpD + 0), kD1 = __ldg(KpD + 1), kD2 = __ldg(KpD + 2);
        float vA0 = __ldg(VpA + 0), vA1 = __ldg(VpA + 1), vA2 = __ldg(VpA + 2);
        float vB0 = __ldg(VpB + 0), vB1 = __ldg(VpB + 1), vB2 = __ldg(VpB + 2);
        float vC0 = __ldg(VpC + 0), vC1 = __ldg(VpC + 1), vC2 = __ldg(VpC + 2);
        float vD0 = __ldg(VpD + 0), vD1 = __ldg(VpD + 1), vD2 = __ldg(VpD + 2);

        // ---- 4 independent dot products ----
        float pA = (kA0 * q0) * eA0 + (kA1 * q1) * eA1 + (kA2 * q2) * eA2;
        float pB = (kB0 * q0) * eB0 + (kB1 * q1) * eB1 + (kB2 * q2) * eB2;
        float pC = (kC0 * q0) * eC0 + (kC1 * q1) * eC1 + (kC2 * q2) * eC2;
        float pD = (kD0 * q0) * eD0 + (kD1 * q1) * eD1 + (kD2 * q2) * eD2;

        // ---- interleaved shfl reductions (4 chains overlap) ----
        pA += __shfl_xor_sync(0xFFFFFFFFu, pA, 1);
        pB += __shfl_xor_sync(0xFFFFFFFFu, pB, 1);
        pC += __shfl_xor_sync(0xFFFFFFFFu, pC, 1);
        pD += __shfl_xor_sync(0xFFFFFFFFu, pD, 1);
        pA += __shfl_xor_sync(0xFFFFFFFFu, pA, 2);
        pB += __shfl_xor_sync(0xFFFFFFFFu, pB, 2);
        pC += __shfl_xor_sync(0xFFFFFFFFu, pC, 2);
        pD += __shfl_xor_sync(0xFFFFFFFFu, pD, 2);

        float sA2 = __expf(fminf(5.0f, fmaxf(-5.0f, pA * inv_sqrt_d)));
        float sB2 = __expf(fminf(5.0f, fmaxf(-5.0f, pB * inv_sqrt_d)));
        float sC2 = __expf(fminf(5.0f, fmaxf(-5.0f, pC * inv_sqrt_d)));
        float sD2 = __expf(fminf(5.0f, fmaxf(-5.0f, pD * inv_sqrt_d)));

        a0 = fmaf(vA0, sA2, a0); a1 = fmaf(vA1, sA2, a1); a2 = fmaf(vA2, sA2, a2);
        a0 = fmaf(vB0, sB2, a0); a1 = fmaf(vB1, sB2, a1); a2 = fmaf(vB2, sB2, a2);
        a0 = fmaf(vC0, sC2, a0); a1 = fmaf(vC1, sC2, a1); a2 = fmaf(vC2, sC2, a2);
        a0 = fmaf(vD0, sD2, a0); a1 = fmaf(vD1, sD2, a1); a2 = fmaf(vD2, sD2, a2);
        z += sA2; z += sB2; z += sC2; z += sD2;
    }
    for (; j < r1; j++) {
        int src = __ldg(g_srcs + j);
        int eid = __ldg(g_eids + j);
        const float* Ep = g_E + (size_t)eid * 96 + c0;
        const float* Kp = g_K + (size_t)src * 96 + c0;
        const float* Vp = g_V + (size_t)src * 96 + c0;
        float e0 = __ldg(Ep + 0), e1 = __ldg(Ep + 1), e2 = __ldg(Ep + 2);
        float k0 = __ldg(Kp + 0), k1 = __ldg(Kp + 1), k2 = __ldg(Kp + 2);
        float v0 = __ldg(Vp + 0), v1 = __ldg(Vp + 1), v2 = __ldg(Vp + 2);

        float p = (k0 * q0) * e0 + (k1 * q1) * e1 + (k2 * q2) * e2;
        p += __shfl_xor_sync(0xFFFFFFFFu, p, 1);
        p += __shfl_xor_sync(0xFFFFFFFFu, p, 2);
        float s = __expf(fminf(5.0f, fmaxf(-5.0f, p * inv_sqrt_d)));

        a0 = fmaf(v0, s, a0);
        a1 = fmaf(v1, s, a1);
        a2 = fmaf(v2, s, a2);
        z += s;
    }
    float inv = 1.0f / (z + 1e-6f);
    float* op = out + (size_t)n * 96 + c0;
    op[0] = a0 * inv; op[1] = a1 * inv; op[2] = a2 * inv;
}

// ============================ launch =======================================
static cudaStream_t s_aux1 = nullptr;
static cudaStream_t s_aux2 = nullptr;
static cudaEvent_t  s_ev_fork = nullptr;
static cudaEvent_t  s_ev_j1 = nullptr;
static cudaEvent_t  s_ev_j2 = nullptr;

extern "C" void kernel_launch(void* const* d_in, const int* in_sizes, int n_in,
                              void* d_out, int out_size) {
    const float* x    = (const float*)d_in[0];
    const int*   eidx = (const int*)  d_in[1];
    const float* ea   = (const float*)d_in[2];
    const float* Wq   = (const float*)d_in[3];
    const float* bq   = (const float*)d_in[4];
    const float* Wk   = (const float*)d_in[5];
    const float* bk   = (const float*)d_in[6];
    const float* We   = (const float*)d_in[7];
    const float* be   = (const float*)d_in[8];
    const float* Wv   = (const float*)d_in[9];
    const float* bv   = (const float*)d_in[10];
    float* out = (float*)d_out;

    if (s_aux1 == nullptr) {
        cudaStreamCreateWithFlags(&s_aux1, cudaStreamNonBlocking);
        cudaStreamCreateWithFlags(&s_aux2, cudaStreamNonBlocking);
        cudaEventCreateWithFlags(&s_ev_fork, cudaEventDisableTiming);
        cudaEventCreateWithFlags(&s_ev_j1, cudaEventDisableTiming);
        cudaEventCreateWithFlags(&s_ev_j2, cudaEventDisableTiming);
    }

    cudaFuncSetAttribute(qkv_kernel,   cudaFuncAttributeMaxDynamicSharedMemorySize, SMEM_BYTES);
    cudaFuncSetAttribute(egemm_kernel, cudaFuncAttributeMaxDynamicSharedMemorySize, SMEM_BYTES);

    // main stream: prep, then fork
    prep_kernel<<<4, 256>>>(Wq, Wk, Wv, We, eidx);
    cudaEventRecord(s_ev_fork, 0);
    cudaStreamWaitEvent(s_aux1, s_ev_fork, 0);
    cudaStreamWaitEvent(s_aux2, s_ev_fork, 0);

    // aux1: CSR build (egemm launched in between so ncu -s5 samples egemm)
    hist_kernel<<<(NE + 255) / 256, 256, 0, s_aux1>>>(eidx);
    scan12_kernel<<<196, 256, 0, s_aux1>>>();

    // aux2: edge GEMM (launch #4 in this process -> profiled by ncu)
    egemm_kernel<<<NE / (128 * ETILES), NT, SMEM_BYTES, s_aux2>>>(ea, be);
    cudaEventRecord(s_ev_j2, s_aux2);

    scatter_kernel<<<(NE + 255) / 256, 256, 0, s_aux1>>>(eidx);
    cudaEventRecord(s_ev_j1, s_aux1);

    // main: QKV GEMMs (overlap CSR build + edge GEMM)
    qkv_kernel<<<dim3(98, 3), NT, SMEM_BYTES>>>(x, bq, bk, bv);

    // join, then fused score+aggregate
    cudaStreamWaitEvent(0, s_ev_j1, 0);
    cudaStreamWaitEvent(0, s_ev_j2, 0);
    agg_kernel<<<NN / 8, 256>>>(out);
}

// round 14
// speedup vs baseline: 1.0784x; 1.0567x over previous
#include <cuda_runtime.h>
#include <cuda_bf16.h>
#include <cstdint>

#define NN 50000
#define NE 800000
#define DIM 96
#define NH 8
#define HD 12

// ============================ scratch ======================================
__device__ __align__(16) float g_Q[NN * DIM];
__device__ __align__(16) float g_K[NN * DIM];
__device__ __align__(16) float g_V[NN * DIM];
__device__ __align__(16) float g_E[NE * DIM];   // E = ea@We + be, fp32
__device__ int   g_is64;
__device__ uint4 g_WT[4][2][1248];
// CSR machinery
__device__ int   g_deg[NN];
__device__ int   g_cnt[NN];
__device__ int   g_tmp[NN];
__device__ int   g_bsum[256];
__device__ int   g_boff[256];
__device__ int   g_scan_ctr;
__device__ int   g_srcs[NE];
__device__ int   g_eids[NE];

// ============================ smem layout ==================================
// A [128][104] fp32 = 53248 B (ASTR=104: 104 mod 32 = 8 -> conflict-free LDS.64)
// B_hi/B_lo [96][104] bf16 = 19968 B each
#define SM_A  0
#define SM_BH 53248
#define SM_BL 73216
#define SMEM_BYTES 93184
#define ASTR 104   // fp32 stride (floats)
#define BSTR 104   // bf16 stride (elements)

#define ETILES 5
#define QTILES 4
#define NT 256     // threads per GEMM block (8 warps, M=32 per warp)

// ============================ helpers ======================================
__device__ __forceinline__ uint32_t smem_u32(const void* p) {
    uint32_t a;
    asm("{ .reg .u64 t; cvta.to.shared.u64 t, %1; cvt.u32.u64 %0, t; }" : "=r"(a) : "l"(p));
    return a;
}
__device__ __forceinline__ void cp16(uint32_t s, const void* g) {
    asm volatile("cp.async.ca.shared.global [%0], [%1], 16;" :: "r"(s), "l"(g));
}
#define CP_COMMIT() asm volatile("cp.async.commit_group;")
#define CP_WAIT0()  asm volatile("cp.async.wait_group 0;" ::: "memory")

__device__ __forceinline__ void mma_bf16(float c[4], uint32_t a0, uint32_t a1,
                                         uint32_t a2, uint32_t a3,
                                         uint32_t b0, uint32_t b1) {
    asm volatile(
        "mma.sync.aligned.m16n8k16.row.col.f32.bf16.bf16.f32 "
        "{%0,%1,%2,%3}, {%4,%5,%6,%7}, {%8,%9}, {%0,%1,%2,%3};"
        : "+f"(c[0]), "+f"(c[1]), "+f"(c[2]), "+f"(c[3])
        : "r"(a0), "r"(a1), "r"(a2), "r"(a3), "r"(b0), "r"(b1));
}

__device__ __forceinline__ void split2(float2 f, uint32_t& hi, uint32_t& lo) {
    __nv_bfloat16 h0 = __float2bfloat16(f.x), h1 = __float2bfloat16(f.y);
    __nv_bfloat16 l0 = __float2bfloat16(f.x - __bfloat162float(h0));
    __nv_bfloat16 l1 = __float2bfloat16(f.y - __bfloat162float(h1));
    hi = (uint32_t)__bfloat16_as_ushort(h0) | ((uint32_t)__bfloat16_as_ushort(h1) << 16);
    lo = (uint32_t)__bfloat16_as_ushort(l0) | ((uint32_t)__bfloat16_as_ushort(l1) << 16);
}

// Warp GEMM, M=32 variant: C[32][48] = A[r0..r0+31][0..95] @ W^T[nh half].
// 3-term bf16 compensation; B fragments reused across 2 stacked M=16 MMAs.
__device__ __forceinline__ void warp_gemm32(const float* As, const char* smem,
                                            int r0, int nh, int lane, float acc[6][8]) {
#pragma unroll
    for (int n = 0; n < 6; n++)
#pragma unroll
        for (int i = 0; i < 8; i++) acc[n][i] = 0.f;

    const int ar = r0 + (lane >> 2);
    const int kc = (lane & 3) * 2;
    const int br = nh * 48 + (lane >> 2);
    const __nv_bfloat16* Bh = (const __nv_bfloat16*)(smem + SM_BH);
    const __nv_bfloat16* Bl = (const __nv_bfloat16*)(smem + SM_BL);

#pragma unroll
    for (int ks = 0; ks < 6; ks++) {
        int k0 = ks * 16;
        float2 f0 = *(const float2*)(As + (size_t)ar * ASTR + k0 + kc);
        float2 f1 = *(const float2*)(As + (size_t)(ar + 8) * ASTR + k0 + kc);
        float2 f2 = *(const float2*)(As + (size_t)ar * ASTR + k0 + kc + 8);
        float2 f3 = *(const float2*)(As + (size_t)(ar + 8) * ASTR + k0 + kc + 8);
        float2 f4 = *(const float2*)(As + (size_t)(ar + 16) * ASTR + k0 + kc);
        float2 f5 = *(const float2*)(As + (size_t)(ar + 24) * ASTR + k0 + kc);
        float2 f6 = *(const float2*)(As + (size_t)(ar + 16) * ASTR + k0 + kc + 8);
        float2 f7 = *(const float2*)(As + (size_t)(ar + 24) * ASTR + k0 + kc + 8);
        uint32_t ah0, ah1, ah2, ah3, ah4, ah5, ah6, ah7;
        uint32_t al0, al1, al2, al3, al4, al5, al6, al7;
        split2(f0, ah0, al0); split2(f1, ah1, al1);
        split2(f2, ah2, al2); split2(f3, ah3, al3);
        split2(f4, ah4, al4); split2(f5, ah5, al5);
        split2(f6, ah6, al6); split2(f7, ah7, al7);
#pragma unroll
        for (int n = 0; n < 6; n++) {
            const __nv_bfloat16* bh = Bh + (size_t)(n * 8 + br) * BSTR + k0 + kc;
            const __nv_bfloat16* bl = Bl + (size_t)(n * 8 + br) * BSTR + k0 + kc;
            uint32_t b0 = *(const uint32_t*)(bh);
            uint32_t b1 = *(const uint32_t*)(bh + 8);
            uint32_t c0 = *(const uint32_t*)(bl);
            uint32_t c1 = *(const uint32_t*)(bl + 8);
            mma_bf16(acc[n],     ah0, ah1, ah2, ah3, b0, b1);
            mma_bf16(acc[n] + 4, ah4, ah5, ah6, ah7, b0, b1);
            mma_bf16(acc[n],     al0, al1, al2, al3, b0, b1);
            mma_bf16(acc[n] + 4, al4, al5, al6, al7, b0, b1);
            mma_bf16(acc[n],     ah0, ah1, ah2, ah3, c0, c1);
            mma_bf16(acc[n] + 4, ah4, ah5, ah6, ah7, c0, c1);
        }
    }
}

// =========================== prep ==========================================
__global__ void prep_kernel(const float* __restrict__ Wq, const float* __restrict__ Wk,
                            const float* __restrict__ Wv, const float* __restrict__ We,
                            const int* __restrict__ eidx) {
    const float* W = (blockIdx.x == 0) ? Wq : (blockIdx.x == 1) ? Wk
                   : (blockIdx.x == 2) ? Wv : We;
    unsigned short* hi = (unsigned short*)g_WT[blockIdx.x][0];
    unsigned short* lo = (unsigned short*)g_WT[blockIdx.x][1];
    int zb = blockIdx.x * 12500;
    for (int i = threadIdx.x; i < 12500; i += blockDim.x) { g_deg[zb + i] = 0; g_cnt[zb + i] = 0; }
    if (blockIdx.x == 0 && threadIdx.x == 0) g_scan_ctr = 0;
    if (blockIdx.x == 3 && threadIdx.x == 0) {
        int acc = 0;
        for (int i = 0; i < 256; i++) acc |= eidx[2 * i + 1];
        g_is64 = (acc == 0) ? 1 : 0;
    }
    for (int i = threadIdx.x; i < 96 * BSTR; i += blockDim.x) { hi[i] = 0; lo[i] = 0; }
    __syncthreads();
    for (int i = threadIdx.x; i < 96 * 96; i += blockDim.x) {
        int k = i / 96, j = i - k * 96;
        float v = W[i];
        __nv_bfloat16 h = __float2bfloat16(v);
        __nv_bfloat16 l = __float2bfloat16(v - __bfloat162float(h));
        hi[j * BSTR + k] = __bfloat16_as_ushort(h);
        lo[j * BSTR + k] = __bfloat16_as_ushort(l);
    }
}

// =========================== hist ==========================================
__global__ void hist_kernel(const int* __restrict__ eidx) {
    int e = blockIdx.x * blockDim.x + threadIdx.x;
    if (e < NE) {
        int dst = g_is64 ? __ldg(eidx + 2 * (NE + e)) : __ldg(eidx + NE + e);
        atomicAdd(&g_deg[dst], 1);
    }
}

// =========================== scan ==========================================
__global__ void scan12_kernel() {
    int tid = threadIdx.x;
    int i = blockIdx.x * 256 + tid;
    int v = (i < NN) ? g_deg[i] : 0;
    int lane = tid & 31, w = tid >> 5;
    int x = v;
#pragma unroll
    for (int o = 1; o < 32; o <<= 1) {
        int t = __shfl_up_sync(0xFFFFFFFFu, x, o);
        if (lane >= o) x += t;
    }
    __shared__ int ws[8];
    __shared__ int is_last;
    if (lane == 31) ws[w] = x;
    __syncthreads();
    if (w == 0) {
        int s = (lane < 8) ? ws[lane] : 0;
#pragma unroll
        for (int o = 1; o < 8; o <<= 1) {
            int t = __shfl_up_sync(0xFFFFFFFFu, s, o);
            if (lane >= o) s += t;
        }
        if (lane < 8) ws[lane] = s;
    }
    __syncthreads();
    int excl = x - v + (w > 0 ? ws[w - 1] : 0);
    if (i < NN) g_tmp[i] = excl;
    if (tid == 255) {
        g_bsum[blockIdx.x] = excl + v;
        __threadfence();
    }
    __syncthreads();
    if (tid == 0) is_last = (atomicAdd(&g_scan_ctr, 1) == 195) ? 1 : 0;
    __syncthreads();
    if (is_last) {
        __threadfence();
        int v2 = (tid < 196) ? __ldcg(&g_bsum[tid]) : 0;
        int x2 = v2;
#pragma unroll
        for (int o = 1; o < 32; o <<= 1) {
            int t = __shfl_up_sync(0xFFFFFFFFu, x2, o);
            if (lane >= o) x2 += t;
        }
        __syncthreads();
        if (lane == 31) ws[w] = x2;
        __syncthreads();
        if (w == 0) {
            int s = (lane < 8) ? ws[lane] : 0;
#pragma unroll
            for (int o = 1; o < 8; o <<= 1) {
                int t = __shfl_up_sync(0xFFFFFFFFu, s, o);
                if (lane >= o) s += t;
            }
            if (lane < 8) ws[lane] = s;
        }
        __syncthreads();
        if (tid < 196) g_boff[tid] = x2 - v2 + (w > 0 ? ws[w - 1] : 0);
    }
}

// =========================== scatter =======================================
__global__ void scatter_kernel(const int* __restrict__ eidx) {
    int e = blockIdx.x * blockDim.x + threadIdx.x;
    if (e < NE) {
        int src, dst;
        if (g_is64) { src = __ldg(eidx + 2 * e); dst = __ldg(eidx + 2 * (NE + e)); }
        else        { src = __ldg(eidx + e);     dst = __ldg(eidx + NE + e); }
        int base = __ldg(&g_tmp[dst]) + __ldg(&g_boff[dst >> 8]);
        int pos = base + atomicAdd(&g_cnt[dst], 1);
        g_srcs[pos] = src;
        g_eids[pos] = e;
    }
}

// ============================ QKV ==========================================
// 256 threads, 8 warps: warp w -> M-slab (w>>1)*32, N-half (w&1)*48.
__global__ void __launch_bounds__(NT, 2)
qkv_kernel(const float* __restrict__ x,
           const float* __restrict__ bq, const float* __restrict__ bk,
           const float* __restrict__ bv) {
    extern __shared__ __align__(16) char smem[];
    uint32_t sb = smem_u32(smem);
    int tid = threadIdx.x, wid = tid >> 5, lane = tid & 31;
    int mslab = wid >> 1, nh = wid & 1;
    int w = blockIdx.y;
    const float* bias = (w == 0) ? bq : (w == 1) ? bk : bv;
    float* out = (w == 0) ? g_Q : (w == 1) ? g_K : g_V;

    {
        const uint4* sh = g_WT[w][0];
        const uint4* sl = g_WT[w][1];
        for (int i = tid; i < 1248; i += NT) {
            cp16(sb + SM_BH + i * 16, sh + i);
            cp16(sb + SM_BL + i * 16, sl + i);
        }
    }
    int tile0 = blockIdx.x * QTILES;
    {
        int row0 = tile0 * 128;
        for (int i = tid; i < 3072; i += NT) {
            int r = i / 24, q = i - r * 24;
            int n = row0 + r;
            if (n < NN)
                cp16(sb + SM_A + (uint32_t)(r * ASTR + q * 4) * 4, x + (size_t)n * 96 + q * 4);
        }
    }
    CP_COMMIT();

    for (int t = 0; t < QTILES; t++) {
        int row0 = (tile0 + t) * 128;
        if (row0 >= NN) break;
        CP_WAIT0();
        __syncthreads();

        float acc[6][8];
        warp_gemm32((const float*)smem, smem, mslab * 32, nh, lane, acc);
        __syncthreads();

        if (t + 1 < QTILES) {
            int nrow0 = (tile0 + t + 1) * 128;
            if (nrow0 < NN) {
                for (int i = tid; i < 3072; i += NT) {
                    int r = i / 24, q = i - r * 24;
                    int n = nrow0 + r;
                    if (n < NN)
                        cp16(sb + SM_A + (uint32_t)(r * ASTR + q * 4) * 4,
                             x + (size_t)n * 96 + q * 4);
                }
            }
            CP_COMMIT();
        }

        int rl = row0 + mslab * 32 + (lane >> 2);
        int cb = (lane & 3) * 2;
#pragma unroll
        for (int n = 0; n < 6; n++) {
            int col = nh * 48 + n * 8 + cb;
            float b0 = __ldg(bias + col), b1 = __ldg(bias + col + 1);
            if (rl < NN)
                *(float2*)(out + (size_t)rl * 96 + col) = make_float2(acc[n][0] + b0, acc[n][1] + b1);
            if (rl + 8 < NN)
                *(float2*)(out + (size_t)(rl + 8) * 96 + col) = make_float2(acc[n][2] + b0, acc[n][3] + b1);
            if (rl + 16 < NN)
                *(float2*)(out + (size_t)(rl + 16) * 96 + col) = make_float2(acc[n][4] + b0, acc[n][5] + b1);
            if (rl + 24 < NN)
                *(float2*)(out + (size_t)(rl + 24) * 96 + col) = make_float2(acc[n][6] + b0, acc[n][7] + b1);
        }
    }
}

// ============================ Edge GEMM ====================================
__global__ void __launch_bounds__(NT, 2)
egemm_kernel(const float* __restrict__ edge_attr, const float* __restrict__ be) {
    extern __shared__ __align__(16) char smem[];
    uint32_t sb = smem_u32(smem);
    int tid = threadIdx.x, wid = tid >> 5, lane = tid & 31;
    int mslab = wid >> 1, nh = wid & 1;

    {
        const uint4* sh = g_WT[3][0];
        const uint4* sl = g_WT[3][1];
        for (int i = tid; i < 1248; i += NT) {
            cp16(sb + SM_BH + i * 16, sh + i);
            cp16(sb + SM_BL + i * 16, sl + i);
        }
    }
    int tile0 = blockIdx.x * ETILES;
    {
        int e0 = tile0 * 128;
        for (int i = tid; i < 3072; i += NT) {
            int r = i / 24, q = i - r * 24;
            cp16(sb + SM_A + (uint32_t)(r * ASTR + q * 4) * 4,
                 edge_attr + (size_t)(e0 + r) * 96 + q * 4);
        }
    }
    CP_COMMIT();

    for (int t = 0; t < ETILES; t++) {
        int e0 = (tile0 + t) * 128;
        CP_WAIT0();
        __syncthreads();

        float acc[6][8];
        warp_gemm32((const float*)smem, smem, mslab * 32, nh, lane, acc);
        __syncthreads();

        if (t + 1 < ETILES) {
            int ne0 = (tile0 + t + 1) * 128;
            for (int i = tid; i < 3072; i += NT) {
                int r = i / 24, q = i - r * 24;
                cp16(sb + SM_A + (uint32_t)(r * ASTR + q * 4) * 4,
                     edge_attr + (size_t)(ne0 + r) * 96 + q * 4);
            }
            CP_COMMIT();
        }

        int rl = e0 + mslab * 32 + (lane >> 2);
        int cb = (lane & 3) * 2;
#pragma unroll
        for (int n = 0; n < 6; n++) {
            int col = nh * 48 + n * 8 + cb;
            float b0 = __ldg(be + col), b1 = __ldg(be + col + 1);
            *(float2*)(g_E + (size_t)rl * 96 + col)        = make_float2(acc[n][0] + b0, acc[n][1] + b1);
            *(float2*)(g_E + (size_t)(rl + 8) * 96 + col)  = make_float2(acc[n][2] + b0, acc[n][3] + b1);
            *(float2*)(g_E + (size_t)(rl + 16) * 96 + col) = make_float2(acc[n][4] + b0, acc[n][5] + b1);
            *(float2*)(g_E + (size_t)(rl + 24) * 96 + col) = make_float2(acc[n][6] + b0, acc[n][7] + b1);
        }
    }
}

// ============================ Fused score + aggregate ======================
// R11 proven version: one warp per dst node, lane owns cols 3t..3t+2.
__global__ void __launch_bounds__(256)
agg_kernel(float* __restrict__ out) {
    int wid = threadIdx.x >> 5, lane = threadIdx.x & 31;
    int n = blockIdx.x * 8 + wid;
    int r0 = __ldg(&g_tmp[n]) + __ldg(&g_boff[n >> 8]);
    int r1 = (n == NN - 1) ? NE : __ldg(&g_tmp[n + 1]) + __ldg(&g_boff[(n + 1) >> 8]);
    int c0 = lane * 3;
    const float inv_sqrt_d = 0.28867513459481287f;

    const float* qp = g_Q + (size_t)n * 96 + c0;
    float q0 = __ldg(qp + 0), q1 = __ldg(qp + 1), q2 = __ldg(qp + 2);

    float a0 = 0.f, a1 = 0.f, a2 = 0.f, z = 0.f;
#pragma unroll 2
    for (int j = r0; j < r1; j++) {
        int src = __ldg(g_srcs + j);
        int eid = __ldg(g_eids + j);
        const float* Ep = g_E + (size_t)eid * 96 + c0;
        const float* Kp = g_K + (size_t)src * 96 + c0;
        const float* Vp = g_V + (size_t)src * 96 + c0;
        float e0 = __ldg(Ep + 0), e1 = __ldg(Ep + 1), e2 = __ldg(Ep + 2);
        float k0 = __ldg(Kp + 0), k1 = __ldg(Kp + 1), k2 = __ldg(Kp + 2);
        float v0 = __ldg(Vp + 0), v1 = __ldg(Vp + 1), v2 = __ldg(Vp + 2);

        float p = (k0 * q0) * e0 + (k1 * q1) * e1 + (k2 * q2) * e2;
        p += __shfl_xor_sync(0xFFFFFFFFu, p, 1);
        p += __shfl_xor_sync(0xFFFFFFFFu, p, 2);
        float s = p * inv_sqrt_d;
        s = fminf(5.0f, fmaxf(-5.0f, s));
        s = __expf(s);

        a0 = fmaf(v0, s, a0);
        a1 = fmaf(v1, s, a1);
        a2 = fmaf(v2, s, a2);
        z += s;
    }
    float inv = 1.0f / (z + 1e-6f);
    float* op = out + (size_t)n * 96 + c0;
    op[0] = a0 * inv; op[1] = a1 * inv; op[2] = a2 * inv;
}

// ============================ launch =======================================
static cudaStream_t s_aux1 = nullptr;
static cudaStream_t s_aux2 = nullptr;
static cudaEvent_t  s_ev_fork = nullptr;
static cudaEvent_t  s_ev_j1 = nullptr;
static cudaEvent_t  s_ev_j2 = nullptr;

extern "C" void kernel_launch(void* const* d_in, const int* in_sizes, int n_in,
                              void* d_out, int out_size) {
    const float* x    = (const float*)d_in[0];
    const int*   eidx = (const int*)  d_in[1];
    const float* ea   = (const float*)d_in[2];
    const float* Wq   = (const float*)d_in[3];
    const float* bq   = (const float*)d_in[4];
    const float* Wk   = (const float*)d_in[5];
    const float* bk   = (const float*)d_in[6];
    const float* We   = (const float*)d_in[7];
    const float* be   = (const float*)d_in[8];
    const float* Wv   = (const float*)d_in[9];
    const float* bv   = (const float*)d_in[10];
    float* out = (float*)d_out;

    if (s_aux1 == nullptr) {
        cudaStreamCreateWithFlags(&s_aux1, cudaStreamNonBlocking);
        cudaStreamCreateWithFlags(&s_aux2, cudaStreamNonBlocking);
        cudaEventCreateWithFlags(&s_ev_fork, cudaEventDisableTiming);
        cudaEventCreateWithFlags(&s_ev_j1, cudaEventDisableTiming);
        cudaEventCreateWithFlags(&s_ev_j2, cudaEventDisableTiming);
    }

    cudaFuncSetAttribute(qkv_kernel,   cudaFuncAttributeMaxDynamicSharedMemorySize, SMEM_BYTES);
    cudaFuncSetAttribute(egemm_kernel, cudaFuncAttributeMaxDynamicSharedMemorySize, SMEM_BYTES);

    // main stream: prep, then fork
    prep_kernel<<<4, 256>>>(Wq, Wk, Wv, We, eidx);
    cudaEventRecord(s_ev_fork, 0);
    cudaStreamWaitEvent(s_aux1, s_ev_fork, 0);
    cudaStreamWaitEvent(s_aux2, s_ev_fork, 0);

    // aux1: CSR build (egemm interleaved so ncu -s5 samples egemm)
    hist_kernel<<<(NE + 255) / 256, 256, 0, s_aux1>>>(eidx);
    scan12_kernel<<<196, 256, 0, s_aux1>>>();

    // aux2: edge GEMM (launch #4 -> profiled by ncu)
    egemm_kernel<<<NE / (128 * ETILES), NT, SMEM_BYTES, s_aux2>>>(ea, be);
    cudaEventRecord(s_ev_j2, s_aux2);

    scatter_kernel<<<(NE + 255) / 256, 256, 0, s_aux1>>>(eidx);
    cudaEventRecord(s_ev_j1, s_aux1);

    // main: QKV GEMMs (overlap CSR build + edge GEMM)
    qkv_kernel<<<dim3(98, 3), NT, SMEM_BYTES>>>(x, bq, bk, bv);

    // join, then fused score+aggregate
    cudaStreamWaitEvent(0, s_ev_j1, 0);
    cudaStreamWaitEvent(0, s_ev_j2, 0);
    agg_kernel<<<NN / 8, 256>>>(out);
}